// round 1
// baseline (speedup 1.0000x reference)
#include <cuda_runtime.h>

#define NROWS 1024
#define HID 128
#define MH 64      // MLP_HIDDEN
#define D32 32
#define OUTD 128

// ---- scratch (device globals; no allocation allowed) ----
__device__ unsigned g_amax[D32];
__device__ unsigned g_cmax[D32];
__device__ unsigned g_hmax[MH];
__device__ float    g_S[D32];
__device__ float    g_T[D32];
__device__ float    g_K[OUTD];

// order-preserving float <-> uint encoding (unsigned compare == float compare)
__device__ __forceinline__ unsigned enc(float f) {
    unsigned u = __float_as_uint(f);
    return (u & 0x80000000u) ? ~u : (u | 0x80000000u);
}
__device__ __forceinline__ float dec(unsigned e) {
    return (e & 0x80000000u) ? __uint_as_float(e & 0x7FFFFFFFu)
                             : __uint_as_float(~e);
}

__global__ void k_init() {
    int t = threadIdx.x;
    if (t < D32) { g_amax[t] = 0u; g_cmax[t] = 0u; }
    if (t < MH)  { g_hmax[t] = 0u; }
}

// blocks 0..63: hidden GEMM (16 rows each) + column max
// block 64    : per-row spatial / velocity projections + global max
__global__ void __launch_bounds__(256) k_phase1(
    const float* __restrict__ hs,
    const float* __restrict__ obs1,
    const float* __restrict__ obs,
    const float* __restrict__ W_sp,
    const float* __restrict__ W_vel,
    const float* __restrict__ W_hid,
    const float* __restrict__ b_hid)
{
    int b = blockIdx.x, t = threadIdx.x;
    if (b == 64) {
        // each thread owns 4 rows
        float2 o[4], v[4];
        #pragma unroll
        for (int r = 0; r < 4; r++) {
            int i = t + 256 * r;
            float2 oo = ((const float2*)obs)[i];
            float2 o1 = ((const float2*)obs1)[i];
            o[r] = oo;
            v[r] = make_float2(4.f * (oo.x - o1.x), 4.f * (oo.y - o1.y));
        }
        for (int d = 0; d < D32; d++) {
            float w0 = W_sp[d],  w1 = W_sp[D32 + d];
            float u0 = W_vel[d], u1 = W_vel[D32 + d];
            float ma = -3.4e38f, mc = -3.4e38f;
            #pragma unroll
            for (int r = 0; r < 4; r++) {
                ma = fmaxf(ma, fmaf(o[r].x, w0, o[r].y * w1));
                mc = fmaxf(mc, fmaf(v[r].x, u0, v[r].y * u1));
            }
            #pragma unroll
            for (int s = 16; s > 0; s >>= 1) {
                ma = fmaxf(ma, __shfl_xor_sync(0xffffffffu, ma, s));
                mc = fmaxf(mc, __shfl_xor_sync(0xffffffffu, mc, s));
            }
            if ((t & 31) == 0) {
                atomicMax(&g_amax[d], enc(ma));
                atomicMax(&g_cmax[d], enc(mc));
            }
        }
    } else {
        __shared__ float hsS[16][HID];   // 8 KB
        __shared__ float red[4][MH];     // 1 KB
        int row0 = b * 16;
        for (int x = t; x < 16 * HID; x += 256)
            hsS[x >> 7][x & 127] = hs[row0 * HID + x];
        __syncthreads();

        int k = t & 63, rg = t >> 6;     // 4 row-groups x 64 k
        float bk = b_hid[k];
        float acc[4] = {bk, bk, bk, bk};
        #pragma unroll 4
        for (int c = 0; c < HID; c++) {
            float w = __ldg(&W_hid[c * MH + k]);   // coalesced across warp
            #pragma unroll
            for (int r = 0; r < 4; r++)
                acc[r] = fmaf(hsS[rg * 4 + r][c], w, acc[r]);
        }
        float m = 0.f;  // relu floor
        #pragma unroll
        for (int r = 0; r < 4; r++) m = fmaxf(m, acc[r]);
        red[rg][k] = m;
        __syncthreads();
        if (rg == 0) {
            float mm = fmaxf(fmaxf(red[0][k], red[1][k]),
                             fmaxf(red[2][k], red[3][k]));
            atomicMax(&g_hmax[k], enc(mm));
        }
    }
}

// decode maxes -> S, T; fold hid_max through W_out[64:,:] into constant K[o]
__global__ void k_phase2(const float* __restrict__ b_sp,
                         const float* __restrict__ b_vel,
                         const float* __restrict__ W_out,
                         const float* __restrict__ b_out)
{
    __shared__ float hm[MH];
    int t = threadIdx.x;  // 128 threads
    if (t < MH) hm[t] = dec(g_hmax[t]);
    if (t < D32) {
        g_S[t] = dec(g_amax[t]) + b_sp[t];
        g_T[t] = dec(g_cmax[t]) + b_vel[t];
    }
    __syncthreads();
    float acc = b_out[t];
    #pragma unroll 4
    for (int k = 0; k < MH; k++)
        acc = fmaf(hm[k], W_out[(64 + k) * OUTD + t], acc);
    g_K[t] = acc;
}

// out[i,o] = sum_{d<64} f[i][d] * W_out[d][o] + K[o]
// f[i][0:32]  = relu(S[d] - a_i[d]),  f[i][32:64] = relu(T[d] - c_i[d])
__global__ void __launch_bounds__(256) k_phase3(
    const float* __restrict__ obs1,
    const float* __restrict__ obs,
    const float* __restrict__ W_sp,
    const float* __restrict__ W_vel,
    const float* __restrict__ W_out,
    float* __restrict__ out)
{
    __shared__ float Wo[64][OUTD];  // 32 KB
    __shared__ float f[16][64];     // 4 KB
    int b = blockIdx.x, t = threadIdx.x;
    int row0 = b * 16;

    for (int x = t; x < 64 * OUTD; x += 256)
        Wo[x >> 7][x & 127] = W_out[x];

    #pragma unroll
    for (int s = 0; s < 4; s++) {
        int slot = t + 256 * s;
        int row = slot >> 6, d = slot & 63;
        int i = row0 + row;
        float2 oo = ((const float2*)obs)[i];
        float val;
        if (d < D32) {
            float a = fmaf(oo.x, W_sp[d], oo.y * W_sp[D32 + d]);
            val = fmaxf(g_S[d] - a, 0.f);
        } else {
            int dd = d - D32;
            float2 o1 = ((const float2*)obs1)[i];
            float vx = 4.f * (oo.x - o1.x), vy = 4.f * (oo.y - o1.y);
            float c = fmaf(vx, W_vel[dd], vy * W_vel[D32 + dd]);
            val = fmaxf(g_T[dd] - c, 0.f);
        }
        f[row][d] = val;
    }
    __syncthreads();

    int o = t & 127, rh = t >> 7;   // 2 row-halves x 128 outputs
    float K = g_K[o];
    float acc[8];
    #pragma unroll
    for (int r = 0; r < 8; r++) acc[r] = K;
    #pragma unroll 4
    for (int d = 0; d < 64; d++) {
        float w = Wo[d][o];                 // conflict-free (o = lane)
        #pragma unroll
        for (int r = 0; r < 8; r++)
            acc[r] = fmaf(f[rh * 8 + r][d], w, acc[r]);  // smem broadcast
    }
    #pragma unroll
    for (int r = 0; r < 8; r++)
        out[(row0 + rh * 8 + r) * OUTD + o] = acc[r];
}

extern "C" void kernel_launch(void* const* d_in, const int* in_sizes, int n_in,
                              void* d_out, int out_size)
{
    const float* hs    = (const float*)d_in[0];
    const float* obs1  = (const float*)d_in[1];
    const float* obs   = (const float*)d_in[2];
    const float* W_sp  = (const float*)d_in[3];
    const float* b_sp  = (const float*)d_in[4];
    const float* W_vel = (const float*)d_in[5];
    const float* b_vel = (const float*)d_in[6];
    const float* W_hid = (const float*)d_in[7];
    const float* b_hid = (const float*)d_in[8];
    const float* W_out = (const float*)d_in[9];
    const float* b_out = (const float*)d_in[10];
    float* out = (float*)d_out;

    k_init<<<1, 128>>>();
    k_phase1<<<65, 256>>>(hs, obs1, obs, W_sp, W_vel, W_hid, b_hid);
    k_phase2<<<1, 128>>>(b_sp, b_vel, W_out, b_out);
    k_phase3<<<64, 256>>>(obs1, obs, W_sp, W_vel, W_out, out);
}

// round 2
// speedup vs baseline: 1.2716x; 1.2716x over previous
#include <cuda_runtime.h>

#define NROWS 1024
#define HID 128
#define MH 64
#define D32 32
#define OUTD 128
#define G1 128   // kernel1 grid (8 rows/block)
#define G2 256   // kernel2 grid (4 rows/block)

// per-block partial maxes: [block][0:64)=hid, [64:96)=a(spatial), [96:128)=c(vel)
// fully overwritten every launch -> no init kernel, graph-deterministic
__device__ float g_part[G1 * 128];

// kernel1: 128 blocks x 8 rows. hidden GEMM (16x? no: 8x128x64) + row projections,
// per-block column maxes -> g_part.
__global__ void __launch_bounds__(256) k1(
    const float* __restrict__ hs,
    const float* __restrict__ obs1,
    const float* __restrict__ obs,
    const float* __restrict__ W_sp,
    const float* __restrict__ W_vel,
    const float* __restrict__ W_hid,
    const float* __restrict__ b_hid)
{
    __shared__ float hsS[8][HID];     // 4 KB
    __shared__ float red[4][MH];      // 1 KB
    __shared__ float sa[8][D32];      // 1 KB
    __shared__ float sc[8][D32];      // 1 KB
    int b = blockIdx.x, t = threadIdx.x;
    int row0 = b * 8;

    #pragma unroll
    for (int x = t; x < 8 * HID; x += 256)
        hsS[x >> 7][x & 127] = hs[row0 * HID + x];

    {   // projections: thread -> (row = t>>5, d = t&31)
        int row = t >> 5, d = t & 31;
        int i = row0 + row;
        float2 oo = ((const float2*)obs)[i];
        float2 o1 = ((const float2*)obs1)[i];
        float a  = fmaf(oo.x, W_sp[d],  oo.y * W_sp[D32 + d]);
        float vx = 4.f * (oo.x - o1.x), vy = 4.f * (oo.y - o1.y);
        float c  = fmaf(vx, W_vel[d], vy * W_vel[D32 + d]);
        sa[row][d] = a;
        sc[row][d] = c;
    }
    __syncthreads();

    int k = t & 63, rg = t >> 6;      // 4 row-groups x 64 k
    float bk = b_hid[k];
    float a0 = bk, a1 = bk;
    #pragma unroll 4
    for (int c = 0; c < HID; c++) {
        float w = __ldg(&W_hid[c * MH + k]);   // coalesced
        a0 = fmaf(hsS[rg * 2][c],     w, a0);  // smem broadcast
        a1 = fmaf(hsS[rg * 2 + 1][c], w, a1);
    }
    red[rg][k] = fmaxf(fmaxf(a0, a1), 0.f);    // relu folded into max
    __syncthreads();

    if (t < 64) {
        float mm = fmaxf(fmaxf(red[0][t], red[1][t]),
                         fmaxf(red[2][t], red[3][t]));
        g_part[b * 128 + t] = mm;
    } else if (t < 96) {
        int d = t - 64;
        float m = sa[0][d];
        #pragma unroll
        for (int r = 1; r < 8; r++) m = fmaxf(m, sa[r][d]);
        g_part[b * 128 + 64 + d] = m;
    } else if (t < 128) {
        int d = t - 96;
        float m = sc[0][d];
        #pragma unroll
        for (int r = 1; r < 8; r++) m = fmaxf(m, sc[r][d]);
        g_part[b * 128 + 96 + d] = m;
    }
}

// kernel2: 256 blocks x 4 rows. Each block: reduce partials (L2-resident),
// build G[4][128] = [relu(S-a) | relu(T-c) | hid_max], then
// out[i,o] = b_out[o] + sum_{d<128} G[i][d] * W_out[d][o]  (single fused loop)
__global__ void __launch_bounds__(256) k2(
    const float* __restrict__ obs1,
    const float* __restrict__ obs,
    const float* __restrict__ W_sp,
    const float* __restrict__ W_vel,
    const float* __restrict__ W_out,
    const float* __restrict__ b_sp,
    const float* __restrict__ b_vel,
    const float* __restrict__ b_out,
    float* __restrict__ out)
{
    __shared__ float red[2][128];
    __shared__ float hmS[MH], SS[D32], TS[D32];
    __shared__ float G[4][128];       // 2 KB
    int b = blockIdx.x, t = threadIdx.x;

    // reduce the 128 per-block partials: 2 halves x 128 cols (coalesced)
    {
        int col = t & 127, half = t >> 7;
        float m = -3.4e38f;
        const float* p = g_part + half * 64 * 128 + col;
        #pragma unroll 8
        for (int q = 0; q < 64; q++)
            m = fmaxf(m, p[q * 128]);
        red[half][col] = m;
    }
    __syncthreads();
    if (t < 128) {
        float v = fmaxf(red[0][t], red[1][t]);
        if (t < 64)       hmS[t]      = v;
        else if (t < 96)  SS[t - 64]  = v + b_sp[t - 64];
        else              TS[t - 96]  = v + b_vel[t - 96];
    }
    __syncthreads();

    int row0 = b * 4;
    #pragma unroll
    for (int s = 0; s < 2; s++) {
        int slot = t + 256 * s;
        int row = slot >> 7, d = slot & 127;
        float val;
        if (d >= 64) {
            val = hmS[d - 64];
        } else {
            int i = row0 + row;
            float2 oo = ((const float2*)obs)[i];
            if (d < D32) {
                float a = fmaf(oo.x, W_sp[d], oo.y * W_sp[D32 + d]);
                val = fmaxf(SS[d] - a, 0.f);
            } else {
                int dd = d - D32;
                float2 o1 = ((const float2*)obs1)[i];
                float vx = 4.f * (oo.x - o1.x), vy = 4.f * (oo.y - o1.y);
                float c = fmaf(vx, W_vel[dd], vy * W_vel[D32 + dd]);
                val = fmaxf(TS[dd] - c, 0.f);
            }
        }
        G[row][d] = val;
    }
    __syncthreads();

    int o = t & 127, rh = t >> 7;     // 2 row-pairs x 128 outputs
    float bo = b_out[o];
    float acc0 = bo, acc1 = bo;
    #pragma unroll 8
    for (int d = 0; d < 128; d++) {
        float w = __ldg(&W_out[d * OUTD + o]);      // L2-resident, coalesced
        acc0 = fmaf(G[rh * 2][d],     w, acc0);     // smem broadcast
        acc1 = fmaf(G[rh * 2 + 1][d], w, acc1);
    }
    out[(row0 + rh * 2)     * OUTD + o] = acc0;
    out[(row0 + rh * 2 + 1) * OUTD + o] = acc1;
}

extern "C" void kernel_launch(void* const* d_in, const int* in_sizes, int n_in,
                              void* d_out, int out_size)
{
    const float* hs    = (const float*)d_in[0];
    const float* obs1  = (const float*)d_in[1];
    const float* obs   = (const float*)d_in[2];
    const float* W_sp  = (const float*)d_in[3];
    const float* b_sp  = (const float*)d_in[4];
    const float* W_vel = (const float*)d_in[5];
    const float* b_vel = (const float*)d_in[6];
    const float* W_hid = (const float*)d_in[7];
    const float* b_hid = (const float*)d_in[8];
    const float* W_out = (const float*)d_in[9];
    const float* b_out = (const float*)d_in[10];
    float* out = (float*)d_out;

    k1<<<G1, 256>>>(hs, obs1, obs, W_sp, W_vel, W_hid, b_hid);
    k2<<<G2, 256>>>(obs1, obs, W_sp, W_vel, W_out, b_sp, b_vel, b_out, out);
}